// round 1
// baseline (speedup 1.0000x reference)
#include <cuda_runtime.h>

// Problem constants (from reference setup_inputs)
#define IMG_H 1024
#define IMG_W 1024
#define IMG_HW (IMG_H * IMG_W)
#define WS 128
#define HALF 64
#define NE 6            // E
#define NF 7            // E + S
#define DH 16
#define NC 512
#define PX_PER_C (WS * WS)       // 16384
#define PROB_ELEMS (NC * PX_PER_C)  // 8,388,608

#define THREADS 256
#define PIX 4
#define PIXB (THREADS * PIX)     // 1024 pixels per block (8 window rows)
#define BLOCKS_X (PX_PER_C / PIXB)  // 16

__global__ __launch_bounds__(THREADS, 1)
void instanseg_kernel(const float* __restrict__ x,
                      const float* __restrict__ sigma,
                      const float* __restrict__ cvec,
                      const float* __restrict__ W1,
                      const float* __restrict__ b1,
                      const float* __restrict__ W2,
                      const float* __restrict__ b2,
                      const float* __restrict__ W3,
                      const float* __restrict__ b3,
                      const int*   __restrict__ cent,
                      float* __restrict__ out,
                      int write_iidd)
{
    __shared__ float w1s[NF * DH];
    __shared__ float w2s[DH * DH];
    __shared__ float b1c[DH];     // b1 - c[cid] @ W1[0:6]  (fused centroid subtraction)
    __shared__ float b2s[DH];
    __shared__ float w3s[DH];
    __shared__ float b3s;
    __shared__ int   cy0s, cx0s;

    const int tid = threadIdx.x;
    const int cid = blockIdx.y;

    if (tid < NF * DH) w1s[tid] = W1[tid];
    w2s[tid] = W2[tid];
    if (tid < DH) {
        b2s[tid] = b2[tid];
        w3s[tid] = W3[tid];
        float acc = b1[tid];
        #pragma unroll
        for (int e = 0; e < NE; e++)
            acc -= cvec[cid * NE + e] * W1[e * DH + tid];
        b1c[tid] = acc;
    }
    if (tid == 0) {
        b3s = b3[0];
        int cy = cent[cid * 2 + 0];
        int cx = cent[cid * 2 + 1];
        cy = min(max(cy, HALF), IMG_H - HALF);
        cx = min(max(cx, HALF), IMG_W - HALF);
        cy0s = cy - HALF;
        cx0s = cx - HALF;
    }
    __syncthreads();

    const int cy0 = cy0s, cx0 = cx0s;
    const int base = blockIdx.x * PIXB;

    // ---- gather inputs (L2-resident; windows overlap heavily) ----
    float xv[PIX][NF];
    #pragma unroll
    for (int i = 0; i < PIX; i++) {
        int pidx = base + i * THREADS + tid;   // pixel within this centroid window
        int gy = pidx >> 7;
        int gx = pidx & (WS - 1);
        int off = (cy0 + gy) * IMG_W + (cx0 + gx);
        #pragma unroll
        for (int k = 0; k < NE; k++)
            xv[i][k] = x[k * IMG_HW + off];
        xv[i][NE] = sigma[off];
    }

    // ---- layer 1: 7 -> 16, bias pre-fused with -c@W1 ----
    float h1[PIX][DH];
    #pragma unroll
    for (int j = 0; j < DH; j++) {
        float bj = b1c[j];
        #pragma unroll
        for (int i = 0; i < PIX; i++) h1[i][j] = bj;
    }
    #pragma unroll
    for (int k = 0; k < NF; k++) {
        #pragma unroll
        for (int j = 0; j < DH; j++) {
            float w = w1s[k * DH + j];
            #pragma unroll
            for (int i = 0; i < PIX; i++)
                h1[i][j] = fmaf(xv[i][k], w, h1[i][j]);
        }
    }
    #pragma unroll
    for (int j = 0; j < DH; j++)
        #pragma unroll
        for (int i = 0; i < PIX; i++)
            h1[i][j] = fmaxf(h1[i][j], 0.0f);

    // ---- layer 2: 16 -> 16 (dominant cost; weight LDS amortized over PIX) ----
    float h2[PIX][DH];
    #pragma unroll
    for (int j = 0; j < DH; j++) {
        float bj = b2s[j];
        #pragma unroll
        for (int i = 0; i < PIX; i++) h2[i][j] = bj;
    }
    #pragma unroll
    for (int k = 0; k < DH; k++) {
        #pragma unroll
        for (int j = 0; j < DH; j++) {
            float w = w2s[k * DH + j];
            #pragma unroll
            for (int i = 0; i < PIX; i++)
                h2[i][j] = fmaf(h1[i][k], w, h2[i][j]);
        }
    }

    // ---- layer 3: 16 -> 1, sigmoid, stores ----
    const float bb3 = b3s;
    #pragma unroll
    for (int i = 0; i < PIX; i++) {
        float z = bb3;
        #pragma unroll
        for (int j = 0; j < DH; j++)
            z = fmaf(fmaxf(h2[i][j], 0.0f), w3s[j], z);
        float p = 1.0f / (1.0f + __expf(-z));

        int pidx = base + i * THREADS + tid;
        int gy = pidx >> 7;
        int gx = pidx & (WS - 1);
        long gidx = (long)cid * PX_PER_C + pidx;
        out[gidx] = p;
        if (write_iidd) {
            out[(long)PROB_ELEMS     + gidx] = (float)cid;
            out[(long)2 * PROB_ELEMS + gidx] = (float)(cy0 + gy);
            out[(long)3 * PROB_ELEMS + gidx] = (float)(cx0 + gx);
        }
    }
}

extern "C" void kernel_launch(void* const* d_in, const int* in_sizes, int n_in,
                              void* d_out, int out_size)
{
    const float* x     = (const float*)d_in[0];
    const float* sigma = (const float*)d_in[1];
    const float* cvec  = (const float*)d_in[2];
    const float* W1    = (const float*)d_in[3];
    const float* b1    = (const float*)d_in[4];
    const float* W2    = (const float*)d_in[5];
    const float* b2    = (const float*)d_in[6];
    const float* W3    = (const float*)d_in[7];
    const float* b3    = (const float*)d_in[8];
    const int*   cent  = (const int*)d_in[9];
    float* out = (float*)d_out;

    // out_size tells us whether the harness wants just prob (8.39M) or
    // prob + iidd concatenated (33.55M).
    int write_iidd = (out_size >= 4 * PROB_ELEMS) ? 1 : 0;

    dim3 grid(BLOCKS_X, NC);
    instanseg_kernel<<<grid, THREADS>>>(x, sigma, cvec, W1, b1, W2, b2, W3, b3,
                                        cent, out, write_iidd);
}

// round 2
// speedup vs baseline: 1.4459x; 1.4459x over previous
#include <cuda_runtime.h>

typedef unsigned long long u64;

// Problem constants (from reference setup_inputs)
#define IMG_H 1024
#define IMG_W 1024
#define IMG_HW (IMG_H * IMG_W)
#define WS 128
#define HALF 64
#define NE 6            // E
#define NF 7            // E + S
#define DH 16
#define NC 512
#define PX_PER_C (WS * WS)          // 16384
#define PROB_ELEMS (NC * PX_PER_C)  // 8,388,608

#define THREADS 256
#define PIX 4
#define PIXB (THREADS * PIX)        // 1024 pixels per block
#define BLOCKS_X (PX_PER_C / PIXB)  // 16

// ---- packed f32x2 helpers (Blackwell FFMA2 path) ----
__device__ __forceinline__ u64 pk2(float lo, float hi) {
    u64 r; asm("mov.b64 %0, {%1, %2};" : "=l"(r) : "f"(lo), "f"(hi)); return r;
}
__device__ __forceinline__ void up2(u64 v, float& a, float& b) {
    asm("mov.b64 {%0, %1}, %2;" : "=f"(a), "=f"(b) : "l"(v));
}
__device__ __forceinline__ u64 fma2(u64 a, u64 b, u64 c) {
    u64 d; asm("fma.rn.f32x2 %0, %1, %2, %3;" : "=l"(d) : "l"(a), "l"(b), "l"(c)); return d;
}
__device__ __forceinline__ u64 relu2(u64 v) {
    float a, b; up2(v, a, b);
    return pk2(fmaxf(a, 0.0f), fmaxf(b, 0.0f));
}

__global__ __launch_bounds__(THREADS, 2)
void instanseg_kernel(const float* __restrict__ x,
                      const float* __restrict__ sigma,
                      const float* __restrict__ cvec,
                      const float* __restrict__ W1,
                      const float* __restrict__ b1,
                      const float* __restrict__ W2,
                      const float* __restrict__ b2,
                      const float* __restrict__ W3,
                      const float* __restrict__ b3,
                      const int*   __restrict__ cent,
                      float* __restrict__ out,
                      int write_iidd)
{
    // Duplicated weights: one LDS.64 feeds both halves of an FFMA2.
    __shared__ float2 w1d[NF * DH];
    __shared__ float2 w2d[DH * DH];
    __shared__ float2 b1cd[DH];    // b1 - c[cid]@W1[0:6], duplicated
    __shared__ float2 b2d[DH];
    __shared__ float  w3s[DH];
    __shared__ float  b3s;
    __shared__ int    cy0s, cx0s;

    const int tid = threadIdx.x;
    const int cid = blockIdx.y;

    if (tid < NF * DH) { float w = W1[tid]; w1d[tid] = make_float2(w, w); }
    { float w = W2[tid]; w2d[tid] = make_float2(w, w); }
    if (tid < DH) {
        float bb = b2[tid]; b2d[tid] = make_float2(bb, bb);
        w3s[tid] = W3[tid];
        float acc = b1[tid];
        #pragma unroll
        for (int e = 0; e < NE; e++)
            acc -= cvec[cid * NE + e] * W1[e * DH + tid];
        b1cd[tid] = make_float2(acc, acc);
    }
    if (tid == 0) {
        b3s = b3[0];
        int cy = cent[cid * 2 + 0];
        int cx = cent[cid * 2 + 1];
        cy = min(max(cy, HALF), IMG_H - HALF);
        cx = min(max(cx, HALF), IMG_W - HALF);
        cy0s = cy - HALF;
        cx0s = cx - HALF;
    }
    __syncthreads();

    const int cy0 = cy0s, cx0 = cx0s;
    const int base = blockIdx.x * PIXB;

    const u64* w1p  = (const u64*)w1d;
    const u64* w2p  = (const u64*)w2d;
    const u64* b1cp = (const u64*)b1cd;
    const u64* b2p  = (const u64*)b2d;

    // ---- pixel offsets ----
    int off[PIX];
    #pragma unroll
    for (int i = 0; i < PIX; i++) {
        int p = base + i * THREADS + tid;
        int gy = p >> 7;
        int gx = p & (WS - 1);
        off[i] = (cy0 + gy) * IMG_W + (cx0 + gx);
    }

    // ---- gather, packed as pixel pairs (0,1) and (2,3) ----
    u64 xp[2][NF];
    #pragma unroll
    for (int k = 0; k < NE; k++) {
        const float* xk = x + k * IMG_HW;
        xp[0][k] = pk2(xk[off[0]], xk[off[1]]);
        xp[1][k] = pk2(xk[off[2]], xk[off[3]]);
    }
    xp[0][NE] = pk2(sigma[off[0]], sigma[off[1]]);
    xp[1][NE] = pk2(sigma[off[2]], sigma[off[3]]);

    // ---- layer 1: 7 -> 16 (bias pre-fused with -c@W1) ----
    u64 h1p[2][DH];
    #pragma unroll
    for (int j = 0; j < DH; j++) {
        u64 b = b1cp[j];
        h1p[0][j] = b; h1p[1][j] = b;
    }
    #pragma unroll
    for (int k = 0; k < NF; k++) {
        #pragma unroll
        for (int j = 0; j < DH; j++) {
            u64 w = w1p[k * DH + j];
            h1p[0][j] = fma2(xp[0][k], w, h1p[0][j]);
            h1p[1][j] = fma2(xp[1][k], w, h1p[1][j]);
        }
    }
    #pragma unroll
    for (int j = 0; j < DH; j++) {
        h1p[0][j] = relu2(h1p[0][j]);
        h1p[1][j] = relu2(h1p[1][j]);
    }

    // ---- layer 2 (j-chunked) + fused relu + layer 3 accumulation ----
    float z[PIX];
    #pragma unroll
    for (int i = 0; i < PIX; i++) z[i] = b3s;

    #pragma unroll
    for (int chunk = 0; chunk < 2; chunk++) {
        u64 h2p[2][8];
        #pragma unroll
        for (int j = 0; j < 8; j++) {
            u64 b = b2p[chunk * 8 + j];
            h2p[0][j] = b; h2p[1][j] = b;
        }
        #pragma unroll
        for (int k = 0; k < DH; k++) {
            #pragma unroll
            for (int j = 0; j < 8; j++) {
                u64 w = w2p[k * DH + chunk * 8 + j];
                h2p[0][j] = fma2(h1p[0][k], w, h2p[0][j]);
                h2p[1][j] = fma2(h1p[1][k], w, h2p[1][j]);
            }
        }
        #pragma unroll
        for (int j = 0; j < 8; j++) {
            float w3 = w3s[chunk * 8 + j];
            float a, b;
            up2(h2p[0][j], a, b);
            z[0] = fmaf(fmaxf(a, 0.0f), w3, z[0]);
            z[1] = fmaf(fmaxf(b, 0.0f), w3, z[1]);
            up2(h2p[1][j], a, b);
            z[2] = fmaf(fmaxf(a, 0.0f), w3, z[2]);
            z[3] = fmaf(fmaxf(b, 0.0f), w3, z[3]);
        }
    }

    // ---- sigmoid + stores ----
    #pragma unroll
    for (int i = 0; i < PIX; i++) {
        float p = __fdividef(1.0f, 1.0f + __expf(-z[i]));
        int pidx = base + i * THREADS + tid;
        int gy = pidx >> 7;
        int gx = pidx & (WS - 1);
        long gidx = (long)cid * PX_PER_C + pidx;
        out[gidx] = p;
        if (write_iidd) {
            out[(long)PROB_ELEMS     + gidx] = (float)cid;
            out[(long)2 * PROB_ELEMS + gidx] = (float)(cy0 + gy);
            out[(long)3 * PROB_ELEMS + gidx] = (float)(cx0 + gx);
        }
    }
}

extern "C" void kernel_launch(void* const* d_in, const int* in_sizes, int n_in,
                              void* d_out, int out_size)
{
    const float* x     = (const float*)d_in[0];
    const float* sigma = (const float*)d_in[1];
    const float* cvec  = (const float*)d_in[2];
    const float* W1    = (const float*)d_in[3];
    const float* b1    = (const float*)d_in[4];
    const float* W2    = (const float*)d_in[5];
    const float* b2    = (const float*)d_in[6];
    const float* W3    = (const float*)d_in[7];
    const float* b3    = (const float*)d_in[8];
    const int*   cent  = (const int*)d_in[9];
    float* out = (float*)d_out;

    int write_iidd = (out_size >= 4 * PROB_ELEMS) ? 1 : 0;

    dim3 grid(BLOCKS_X, NC);
    instanseg_kernel<<<grid, THREADS>>>(x, sigma, cvec, W1, b1, W2, b2, W3, b3,
                                        cent, out, write_iidd);
}

// round 3
// speedup vs baseline: 1.5443x; 1.0681x over previous
#include <cuda_runtime.h>

typedef unsigned long long u64;

#define IMG_H 1024
#define IMG_W 1024
#define IMG_HW (IMG_H * IMG_W)
#define WS 128
#define HALF 64
#define NE 6
#define NF 7
#define DH 16
#define NC 512
#define PX_PER_C (WS * WS)
#define PROB_ELEMS (NC * PX_PER_C)

#define THREADS 256
#define PIX 4
#define PIXB (THREADS * PIX)
#define BLOCKS_X (PX_PER_C / PIXB)

// ---- packed f32x2 helpers ----
__device__ __forceinline__ u64 pk2(float lo, float hi) {
    u64 r; asm("mov.b64 %0, {%1, %2};" : "=l"(r) : "f"(lo), "f"(hi)); return r;
}
__device__ __forceinline__ void up2(u64 v, float& a, float& b) {
    asm("mov.b64 {%0, %1}, %2;" : "=f"(a), "=f"(b) : "l"(v));
}
__device__ __forceinline__ u64 fma2(u64 a, u64 b, u64 c) {
    u64 d; asm("fma.rn.f32x2 %0, %1, %2, %3;" : "=l"(d) : "l"(a), "l"(b), "l"(c)); return d;
}
__device__ __forceinline__ u64 relu2(u64 v) {
    float a, b; up2(v, a, b);
    return pk2(fmaxf(a, 0.0f), fmaxf(b, 0.0f));
}

__global__ __launch_bounds__(THREADS, 2)
void instanseg_kernel(const float* __restrict__ x,
                      const float* __restrict__ sigma,
                      const float* __restrict__ cvec,
                      const float* __restrict__ W1,
                      const float* __restrict__ b1,
                      const float* __restrict__ W2,
                      const float* __restrict__ b2,
                      const float* __restrict__ W3,
                      const float* __restrict__ b3,
                      const int*   __restrict__ cent,
                      float* __restrict__ out,
                      int write_iidd)
{
    // Weight layout: float4 = (w_{2j}, w_{2j}, w_{2j+1}, w_{2j+1}).
    // One LDS.128 yields TWO duplicated FFMA2 operands.
    __shared__ __align__(16) float4 w1q[NF * DH / 2];   // 56
    __shared__ __align__(16) float4 w2q[DH * DH / 2];   // 128
    __shared__ __align__(16) float2 b1cd[DH];           // b1 - c@W1[0:6], duplicated
    __shared__ __align__(16) float2 b2d[DH];
    __shared__ float  w3s[DH];
    __shared__ float  b3s;
    __shared__ int    cy0s, cx0s;

    const int tid = threadIdx.x;
    const int cid = blockIdx.y;

    if (tid < DH * DH / 2) {
        int k = tid >> 3, jj = tid & 7;
        float wa = W2[k * DH + 2 * jj];
        float wb = W2[k * DH + 2 * jj + 1];
        w2q[tid] = make_float4(wa, wa, wb, wb);
    }
    if (tid < NF * DH / 2) {
        int k = tid >> 3, jj = tid & 7;
        float wa = W1[k * DH + 2 * jj];
        float wb = W1[k * DH + 2 * jj + 1];
        w1q[tid] = make_float4(wa, wa, wb, wb);
    }
    if (tid < DH) {
        float bb = b2[tid]; b2d[tid] = make_float2(bb, bb);
        w3s[tid] = W3[tid];
        float acc = b1[tid];
        #pragma unroll
        for (int e = 0; e < NE; e++)
            acc -= cvec[cid * NE + e] * W1[e * DH + tid];
        b1cd[tid] = make_float2(acc, acc);
    }
    if (tid == 0) {
        b3s = b3[0];
        int cy = cent[cid * 2 + 0];
        int cx = cent[cid * 2 + 1];
        cy = min(max(cy, HALF), IMG_H - HALF);
        cx = min(max(cx, HALF), IMG_W - HALF);
        cy0s = cy - HALF;
        cx0s = cx - HALF;
    }
    __syncthreads();

    const int cy0 = cy0s, cx0 = cx0s;
    const int base = blockIdx.x * PIXB;

    const ulonglong2* w1p  = (const ulonglong2*)w1q;
    const ulonglong2* w2p  = (const ulonglong2*)w2q;
    const u64*        b1cp = (const u64*)b1cd;
    const u64*        b2p  = (const u64*)b2d;

    // ---- pixel offsets ----
    int off[PIX];
    #pragma unroll
    for (int i = 0; i < PIX; i++) {
        int p = base + i * THREADS + tid;
        int gy = p >> 7;
        int gx = p & (WS - 1);
        off[i] = (cy0 + gy) * IMG_W + (cx0 + gx);
    }

    // ---- gather: pixel pairs (0,1), (2,3) ----
    u64 xp[2][NF];
    #pragma unroll
    for (int k = 0; k < NE; k++) {
        const float* xk = x + k * IMG_HW;
        xp[0][k] = pk2(xk[off[0]], xk[off[1]]);
        xp[1][k] = pk2(xk[off[2]], xk[off[3]]);
    }
    xp[0][NE] = pk2(sigma[off[0]], sigma[off[1]]);
    xp[1][NE] = pk2(sigma[off[2]], sigma[off[3]]);

    // ---- layer 1: 7 -> 16 ----
    u64 h1p[2][DH];
    #pragma unroll
    for (int j = 0; j < DH; j++) {
        u64 b = b1cp[j];
        h1p[0][j] = b; h1p[1][j] = b;
    }
    #pragma unroll
    for (int k = 0; k < NF; k++) {
        #pragma unroll
        for (int jj = 0; jj < 8; jj++) {
            ulonglong2 w = w1p[k * 8 + jj];
            h1p[0][2*jj]   = fma2(xp[0][k], w.x, h1p[0][2*jj]);
            h1p[1][2*jj]   = fma2(xp[1][k], w.x, h1p[1][2*jj]);
            h1p[0][2*jj+1] = fma2(xp[0][k], w.y, h1p[0][2*jj+1]);
            h1p[1][2*jj+1] = fma2(xp[1][k], w.y, h1p[1][2*jj+1]);
        }
    }
    #pragma unroll
    for (int j = 0; j < DH; j++) {
        h1p[0][j] = relu2(h1p[0][j]);
        h1p[1][j] = relu2(h1p[1][j]);
    }

    // ---- layer 2 (j-chunked by 8) + fused relu + layer 3 ----
    float z[PIX];
    #pragma unroll
    for (int i = 0; i < PIX; i++) z[i] = b3s;

    #pragma unroll
    for (int chunk = 0; chunk < 2; chunk++) {
        u64 h2p[2][8];
        #pragma unroll
        for (int j = 0; j < 8; j++) {
            u64 b = b2p[chunk * 8 + j];
            h2p[0][j] = b; h2p[1][j] = b;
        }
        #pragma unroll
        for (int k = 0; k < DH; k++) {
            #pragma unroll
            for (int jj = 0; jj < 4; jj++) {
                ulonglong2 w = w2p[k * 8 + chunk * 4 + jj];
                h2p[0][2*jj]   = fma2(h1p[0][k], w.x, h2p[0][2*jj]);
                h2p[1][2*jj]   = fma2(h1p[1][k], w.x, h2p[1][2*jj]);
                h2p[0][2*jj+1] = fma2(h1p[0][k], w.y, h2p[0][2*jj+1]);
                h2p[1][2*jj+1] = fma2(h1p[1][k], w.y, h2p[1][2*jj+1]);
            }
        }
        #pragma unroll
        for (int j = 0; j < 8; j++) {
            float w3 = w3s[chunk * 8 + j];
            float a, b;
            up2(h2p[0][j], a, b);
            z[0] = fmaf(fmaxf(a, 0.0f), w3, z[0]);
            z[1] = fmaf(fmaxf(b, 0.0f), w3, z[1]);
            up2(h2p[1][j], a, b);
            z[2] = fmaf(fmaxf(a, 0.0f), w3, z[2]);
            z[3] = fmaf(fmaxf(b, 0.0f), w3, z[3]);
        }
    }

    // ---- sigmoid + stores ----
    #pragma unroll
    for (int i = 0; i < PIX; i++) {
        float p = __fdividef(1.0f, 1.0f + __expf(-z[i]));
        int pidx = base + i * THREADS + tid;
        int gy = pidx >> 7;
        int gx = pidx & (WS - 1);
        long gidx = (long)cid * PX_PER_C + pidx;
        out[gidx] = p;
        if (write_iidd) {
            out[(long)PROB_ELEMS     + gidx] = (float)cid;
            out[(long)2 * PROB_ELEMS + gidx] = (float)(cy0 + gy);
            out[(long)3 * PROB_ELEMS + gidx] = (float)(cx0 + gx);
        }
    }
}

extern "C" void kernel_launch(void* const* d_in, const int* in_sizes, int n_in,
                              void* d_out, int out_size)
{
    const float* x     = (const float*)d_in[0];
    const float* sigma = (const float*)d_in[1];
    const float* cvec  = (const float*)d_in[2];
    const float* W1    = (const float*)d_in[3];
    const float* b1    = (const float*)d_in[4];
    const float* W2    = (const float*)d_in[5];
    const float* b2    = (const float*)d_in[6];
    const float* W3    = (const float*)d_in[7];
    const float* b3    = (const float*)d_in[8];
    const int*   cent  = (const int*)d_in[9];
    float* out = (float*)d_out;

    int write_iidd = (out_size >= 4 * PROB_ELEMS) ? 1 : 0;

    dim3 grid(BLOCKS_X, NC);
    instanseg_kernel<<<grid, THREADS>>>(x, sigma, cvec, W1, b1, W2, b2, W3, b3,
                                        cent, out, write_iidd);
}